// round 16
// baseline (speedup 1.0000x reference)
#include <cuda_runtime.h>
#include <cstdint>

// CrossNet collapsed form (exact algebra):
//   out = c3 * x0 + D;  t_l = x0 . w_l;  c recurrence with constants
//   e1 = B0.w1, e2 = (B0+B1).w2, D = B0+B1+B2 (computed per-block in staging).
//
// This round: TWO rows per warp, fully interleaved register chains (6 dot
// accumulator chains + 6 interleaved SHFL ladders + 16 front-loaded LDG.128)
// to widen the latency-bound serial chain. redux.f32 reverted (not on sm_103).

#define CN_DIM 1024
#define CN_ORDER 3
#define CN_THREADS 256
#define CN_WARPS (CN_THREADS / 32)
#define CN_ROWS_PER_BLOCK (CN_WARPS * 2)   // 16
#define CN_VEC (CN_DIM / 4)                // 256 float4 per row
#define CN_V_PER_LANE 8                    // 256 / 32 lanes

// 16-byte vector viewed as two packed f32x2 halves (register pairs).
struct __align__(16) P2 { unsigned long long a, b; };

__device__ __forceinline__ unsigned long long fma2(unsigned long long x,
                                                   unsigned long long y,
                                                   unsigned long long z)
{
    unsigned long long d;
    asm("fma.rn.f32x2 %0, %1, %2, %3;" : "=l"(d) : "l"(x), "l"(y), "l"(z));
    return d;
}

__device__ __forceinline__ unsigned long long pack2(float lo, float hi)
{
    unsigned long long r;
    asm("mov.b64 %0, {%1, %2};" : "=l"(r) : "f"(lo), "f"(hi));
    return r;
}

__device__ __forceinline__ float sum2(unsigned long long v)
{
    float lo, hi;
    asm("mov.b64 {%0, %1}, %2;" : "=f"(lo), "=f"(hi) : "l"(v));
    return lo + hi;
}

__global__ __launch_bounds__(CN_THREADS, 2)
void crossnet_fused_kernel(const float* __restrict__ x0,
                           const float* __restrict__ W,
                           const float* __restrict__ B,
                           float* __restrict__ out,
                           int batch)
{
    __shared__ float sW[CN_ORDER * CN_DIM];
    __shared__ float sD[CN_DIM];
    __shared__ float sE[2];
    __shared__ float red1[CN_WARPS];
    __shared__ float red2[CN_WARPS];

    const int tid  = threadIdx.x;
    const int warp = tid >> 5;
    const int lane = tid & 31;
    // two rows per warp: base + warp and base + warp + 8
    const int row0 = blockIdx.x * CN_ROWS_PER_BLOCK + warp;
    const int row1 = row0 + CN_WARPS;
    const bool a0 = (row0 < batch);
    const bool a1 = (row1 < batch);

    // Fire BOTH rows' loads first: 16 independent LDG.128 per lane.
    const P2* __restrict__ xr0 = (const P2*)(x0 + (size_t)(a0 ? row0 : 0) * CN_DIM);
    const P2* __restrict__ xr1 = (const P2*)(x0 + (size_t)(a1 ? row1 : 0) * CN_DIM);
    P2 xA[CN_V_PER_LANE], xB[CN_V_PER_LANE];
    #pragma unroll
    for (int i = 0; i < CN_V_PER_LANE; i++) {
        xA[i] = xr0[i * 32 + lane];
        xB[i] = xr1[i * 32 + lane];
    }

    // ---- staging: W -> smem; compute D, e1, e2 from B/W (L2-hit reads) ----
    {
        const int i = tid;  // CN_VEC == CN_THREADS: one float4 per thread
        const float4* gW = (const float4*)W;
        float4 w0 = gW[i];
        float4 w1 = gW[CN_VEC + i];
        float4 w2 = gW[2 * CN_VEC + i];
        ((float4*)sW)[i]              = w0;
        ((float4*)sW)[CN_VEC + i]     = w1;
        ((float4*)sW)[2 * CN_VEC + i] = w2;

        const float4* gB = (const float4*)B;
        float4 b0 = gB[i];
        float4 b1 = gB[CN_VEC + i];
        float4 b2 = gB[2 * CN_VEC + i];

        float p1 = 0.f;
        p1 = fmaf(b0.x, w1.x, p1); p1 = fmaf(b0.y, w1.y, p1);
        p1 = fmaf(b0.z, w1.z, p1); p1 = fmaf(b0.w, w1.w, p1);
        float4 d2 = make_float4(b0.x + b1.x, b0.y + b1.y, b0.z + b1.z, b0.w + b1.w);
        float p2 = 0.f;
        p2 = fmaf(d2.x, w2.x, p2); p2 = fmaf(d2.y, w2.y, p2);
        p2 = fmaf(d2.z, w2.z, p2); p2 = fmaf(d2.w, w2.w, p2);
        ((float4*)sD)[i] = make_float4(d2.x + b2.x, d2.y + b2.y,
                                       d2.z + b2.z, d2.w + b2.w);

        #pragma unroll
        for (int off = 16; off > 0; off >>= 1) {
            p1 += __shfl_xor_sync(0xffffffffu, p1, off);
            p2 += __shfl_xor_sync(0xffffffffu, p2, off);
        }
        if (lane == 0) { red1[warp] = p1; red2[warp] = p2; }
    }
    __syncthreads();
    if (tid == 0) {
        float e1 = 0.f, e2 = 0.f;
        #pragma unroll
        for (int w = 0; w < CN_WARPS; w++) { e1 += red1[w]; e2 += red2[w]; }
        sE[0] = e1; sE[1] = e2;
    }
    __syncthreads();
    if (!a0) return;   // row1 >= batch implies nothing else for this warp either

    const float e1 = sE[0], e2 = sE[1];
    const P2* w0p = (const P2*)(sW + 0 * CN_DIM);
    const P2* w1p = (const P2*)(sW + 1 * CN_DIM);
    const P2* w2p = (const P2*)(sW + 2 * CN_DIM);

    // six dot chains (3 layers x 2 rows), interleaved
    unsigned long long sA0 = 0ull, sA1 = 0ull, sA2 = 0ull;
    unsigned long long sB0 = 0ull, sB1 = 0ull, sB2 = 0ull;
    #pragma unroll
    for (int i = 0; i < CN_V_PER_LANE; i++) {
        P2 wv0 = w0p[i * 32 + lane];
        P2 wv1 = w1p[i * 32 + lane];
        P2 wv2 = w2p[i * 32 + lane];
        P2 xa = xA[i], xb = xB[i];
        sA0 = fma2(xa.a, wv0.a, sA0); sA0 = fma2(xa.b, wv0.b, sA0);
        sB0 = fma2(xb.a, wv0.a, sB0); sB0 = fma2(xb.b, wv0.b, sB0);
        sA1 = fma2(xa.a, wv1.a, sA1); sA1 = fma2(xa.b, wv1.b, sA1);
        sB1 = fma2(xb.a, wv1.a, sB1); sB1 = fma2(xb.b, wv1.b, sB1);
        sA2 = fma2(xa.a, wv2.a, sA2); sA2 = fma2(xa.b, wv2.b, sA2);
        sB2 = fma2(xb.a, wv2.a, sB2); sB2 = fma2(xb.b, wv2.b, sB2);
    }
    float tA0 = sum2(sA0), tA1 = sum2(sA1), tA2 = sum2(sA2);
    float tB0 = sum2(sB0), tB1 = sum2(sB1), tB2 = sum2(sB2);

    // six interleaved SHFL ladders — latency amortized across chains
    #pragma unroll
    for (int off = 16; off > 0; off >>= 1) {
        tA0 += __shfl_xor_sync(0xffffffffu, tA0, off);
        tB0 += __shfl_xor_sync(0xffffffffu, tB0, off);
        tA1 += __shfl_xor_sync(0xffffffffu, tA1, off);
        tB1 += __shfl_xor_sync(0xffffffffu, tB1, off);
        tA2 += __shfl_xor_sync(0xffffffffu, tA2, off);
        tB2 += __shfl_xor_sync(0xffffffffu, tB2, off);
    }

    // scalar recurrences
    float cA = 1.0f + tA0;
    cA = fmaf(cA, tA1, cA) + e1;
    cA = fmaf(cA, tA2, cA) + e2;
    float cB = 1.0f + tB0;
    cB = fmaf(cB, tB1, cB) + e1;
    cB = fmaf(cB, tB2, cB) + e2;

    // epilogue: out = c * x0 + D for both rows, interleaved
    const unsigned long long cpA = pack2(cA, cA);
    const unsigned long long cpB = pack2(cB, cB);
    const P2* dv = (const P2*)sD;
    P2* __restrict__ o0 = (P2*)(out + (size_t)row0 * CN_DIM);
    P2* __restrict__ o1 = (P2*)(out + (size_t)row1 * CN_DIM);
    #pragma unroll
    for (int i = 0; i < CN_V_PER_LANE; i++) {
        P2 d = dv[i * 32 + lane];
        P2 oa, ob;
        oa.a = fma2(cpA, xA[i].a, d.a);
        oa.b = fma2(cpA, xA[i].b, d.b);
        o0[i * 32 + lane] = oa;
        if (a1) {
            ob.a = fma2(cpB, xB[i].a, d.a);
            ob.b = fma2(cpB, xB[i].b, d.b);
            o1[i * 32 + lane] = ob;
        }
    }
}

extern "C" void kernel_launch(void* const* d_in, const int* in_sizes, int n_in,
                              void* d_out, int out_size)
{
    const float* x0 = (const float*)d_in[0];
    const float* W  = (const float*)d_in[1];
    const float* B  = (const float*)d_in[2];
    float* out      = (float*)d_out;

    const int batch = in_sizes[0] / CN_DIM;
    const int grid  = (batch + CN_ROWS_PER_BLOCK - 1) / CN_ROWS_PER_BLOCK;

    crossnet_fused_kernel<<<grid, CN_THREADS>>>(x0, W, B, out, batch);
}